// round 15
// baseline (speedup 1.0000x reference)
#include <cuda_runtime.h>
#include <cuda_bf16.h>
#include <float.h>
#include <math.h>

#define S 2048
#define D 1024
#define NMEM 32
#define PATCH 32
#define RTILES 64                 // 32-row tiles per memory
#define NBLK 148                  // 1 block per SM: barrier-safe by construction
#define CANDMAX 320

// ---------------- scratch (static device globals; no allocation) ----------------
__device__ float g_entropy [NMEM * S];
__device__ float g_entropy2[S];
__device__ float g_part    [(NMEM + 1) * RTILES * D];   // tile partial colsums
__device__ float g_colmean [(NMEM + 1) * D];
__device__ float g_agg     [S * D];             // query + patches (= 33*aggregated)
__device__ float g_h1p     [32 * (NMEM + 1) * 128];
__device__ float g_emb     [(NMEM + 1) * D];
__device__ float g_norm8   [(NMEM + 1) * 8];
__device__ int   g_fidx    [PATCH];
__device__ unsigned g_cnt  = 0;
__device__ volatile unsigned g_gen;             // monotonic across replays

struct TopkScratch {
    int bins[1024];
    unsigned long long cb[CANDMAX];
    float rmin[8], rmax[8];
    float vmin, vmax;
    int cnt, thr, total;
};

__device__ __forceinline__ float trunc_clip(float x)
{
    return truncf(fminf(fmaxf(x, -128.f), 127.f));
}

// ---------------- cp.async helpers --------------------------------------------------
__device__ __forceinline__ void cp_async16(float* sdst, const float* gsrc)
{
    unsigned sa = (unsigned)__cvta_generic_to_shared(sdst);
    asm volatile("cp.async.cg.shared.global [%0], [%1], 16;" :: "r"(sa), "l"(gsrc) : "memory");
}
// one 1KB chunk (256 floats): lane l copies 2 x 16B
__device__ __forceinline__ void issue_chunk1k(const float* g, float* slot, int l)
{
    cp_async16(slot + l * 4,       g + l * 4);
    cp_async16(slot + l * 4 + 128, g + l * 4 + 128);
    asm volatile("cp.async.commit_group;" ::: "memory");
}

// ---------------- grid barrier (148 blocks, 1/SM, always co-resident) ---------------
__device__ __forceinline__ void grid_barrier()
{
    __threadfence();
    __syncthreads();
    if (threadIdx.x == 0) {
        const unsigned gen0 = g_gen;
        __threadfence();
        if (atomicAdd(&g_cnt, 1) == NBLK - 1) {
            atomicExch(&g_cnt, 0);
            __threadfence();
            atomicAdd((unsigned*)&g_gen, 1);
        } else {
            while (g_gen == gen0) { __nanosleep(64); }
        }
    }
    __syncthreads();
    __threadfence();
}

// ---------------- histogram threshold (warp 0) --------------------------------------
__device__ __forceinline__ void hist_threshold(TopkScratch* sc, int t)
{
    const int w = t >> 5, l = t & 31;
    if (w == 0) {
        int gs = 0;
#pragma unroll
        for (int k = 0; k < 32; k++) gs += sc->bins[l * 32 + k];
        int suf = gs;
#pragma unroll
        for (int off = 1; off < 32; off <<= 1) {
            int o = __shfl_down_sync(0xffffffffu, suf, off);
            if (l + off < 32) suf += o;
        }
        int sufn = __shfl_down_sync(0xffffffffu, suf, 1);
        if (l == 31) sufn = 0;
        if (suf >= PATCH && sufn < PATCH) {
            int c = sufn, bb = 0;
            for (int k = 31; k >= 0; k--) {
                c += sc->bins[l * 32 + k];
                if (c >= PATCH) { bb = l * 32 + k; break; }
            }
            sc->thr = bb; sc->total = c;
        }
    }
}

// ---------------- 128-thread exact top-32 of 2048 non-negative floats ---------------
__device__ __noinline__ void topk_hist128(const float* __restrict__ e, int* rows_s,
                                          TopkScratch* sc)
{
    const int t = threadIdx.x, w = t >> 5, l = t & 31;
    float v[16];
    float mn = FLT_MAX, mx = -FLT_MAX;
#pragma unroll
    for (int j = 0; j < 16; j++) {
        v[j] = e[t + 128 * j];
        mn = fminf(mn, v[j]);
        mx = fmaxf(mx, v[j]);
    }
#pragma unroll
    for (int off = 16; off; off >>= 1) {
        mn = fminf(mn, __shfl_xor_sync(0xffffffffu, mn, off));
        mx = fmaxf(mx, __shfl_xor_sync(0xffffffffu, mx, off));
    }
    if (l == 0) { sc->rmin[w] = mn; sc->rmax[w] = mx; }
#pragma unroll
    for (int j = 0; j < 8; j++) sc->bins[t + 128 * j] = 0;
    if (t == 0) sc->cnt = 0;
    __syncthreads();
    if (t == 0) {
        float a = sc->rmin[0], b = sc->rmax[0];
#pragma unroll
        for (int j = 1; j < 4; j++) { a = fminf(a, sc->rmin[j]); b = fmaxf(b, sc->rmax[j]); }
        sc->vmin = a; sc->vmax = b;
    }
    __syncthreads();
    const float vmin = sc->vmin;
    const float scale = 1023.0f / fmaxf(sc->vmax - vmin, 1e-30f);
    int bn[16];
#pragma unroll
    for (int j = 0; j < 16; j++) {
        int b = (int)((v[j] - vmin) * scale);
        bn[j] = b < 0 ? 0 : (b > 1023 ? 1023 : b);
        atomicAdd(&sc->bins[bn[j]], 1);
    }
    __syncthreads();
    hist_threshold(sc, t);
    __syncthreads();
    const int thr = sc->thr, total = sc->total;
    if (total <= CANDMAX) {
#pragma unroll
        for (int j = 0; j < 16; j++) {
            if (bn[j] >= thr) {
                int p = atomicAdd(&sc->cnt, 1);
                sc->cb[p] = ((unsigned long long)__float_as_uint(v[j]) << 32)
                            | (unsigned)(~(t + 128 * j));
            }
        }
        __syncthreads();
        for (int i = t; i < total; i += 128) {
            const unsigned long long k = sc->cb[i];
            int r = 0;
            for (int q = 0; q < total; q++) r += (sc->cb[q] > k) ? 1 : 0;
            if (r < PATCH) rows_s[r] = (int)(~(unsigned)k);
        }
        __syncthreads();
    } else {
        // exact fallback (degenerate data only)
#pragma unroll 1
        for (int j = 0; j < 16; j++) {
            const int idx = t + 128 * j;
            const unsigned long long k =
                ((unsigned long long)__float_as_uint(v[j]) << 32) | (unsigned)(~idx);
            int r = 0;
            for (int i = 0; i < S; i++) {
                const unsigned long long kk =
                    ((unsigned long long)__float_as_uint(e[i]) << 32) | (unsigned)(~i);
                r += (kk > k) ? 1 : 0;
            }
            if (r < PATCH) rows_s[r] = idx;
        }
        __syncthreads();
    }
}

// ---------------- stream one 32-row tile (1KB chunks, 8-slot ring, 6 in flight) -----
__device__ __noinline__ void stream_tile(const float* __restrict__ mem, int tileg,
                                         float* sm)
{
    const int t = threadIdx.x, w = t >> 5, l = t & 31;
    const int n    = tileg >> 6;
    const int tile = tileg & (RTILES - 1);
    const int row0 = tile * 32 + w * 8;
    const float* rowbase = mem + (size_t)n * S * D + (size_t)row0 * D;
    float* ring = sm + w * 2048;            // 8 slots x 256 floats

    // prime 7 chunks (chunk c: row c>>2, quarter c&3)
#pragma unroll
    for (int c = 0; c < 7; c++)
        issue_chunk1k(rowbase + (size_t)(c >> 2) * D + (c & 3) * 256,
                      ring + (c & 7) * 256, l);

    float4 colacc[8];
#pragma unroll
    for (int j = 0; j < 8; j++) colacc[j] = make_float4(0.f, 0.f, 0.f, 0.f);
    float s1[8], s2[8];
#pragma unroll
    for (int k = 0; k < 8; k++) { s1[k] = 0.f; s2[k] = 0.f; }

#pragma unroll
    for (int c = 0; c < 32; c++) {
        if (c <= 25)      asm volatile("cp.async.wait_group 6;" ::: "memory");
        else if (c == 26) asm volatile("cp.async.wait_group 5;" ::: "memory");
        else if (c == 27) asm volatile("cp.async.wait_group 4;" ::: "memory");
        else if (c == 28) asm volatile("cp.async.wait_group 3;" ::: "memory");
        else if (c == 29) asm volatile("cp.async.wait_group 2;" ::: "memory");
        else if (c == 30) asm volatile("cp.async.wait_group 1;" ::: "memory");
        else              asm volatile("cp.async.wait_group 0;" ::: "memory");
        // slot data is thread-private (same lane wrote it) -> no barrier
        const float4* rp = reinterpret_cast<const float4*>(ring + (c & 7) * 256);
        float4 x0 = rp[l], x1 = rp[l + 32];
        const int q2 = (c & 3) * 2;
        colacc[q2].x += x0.x; colacc[q2].y += x0.y;
        colacc[q2].z += x0.z; colacc[q2].w += x0.w;
        colacc[q2 + 1].x += x1.x; colacc[q2 + 1].y += x1.y;
        colacc[q2 + 1].z += x1.z; colacc[q2 + 1].w += x1.w;
        float a = ((x0.x + x0.y) + (x0.z + x0.w)) + ((x1.x + x1.y) + (x1.z + x1.w));
        float b = ((x0.x * x0.x + x0.y * x0.y) + (x0.z * x0.z + x0.w * x0.w)) +
                  ((x1.x * x1.x + x1.y * x1.y) + (x1.z * x1.z + x1.w * x1.w));
        s1[c >> 2] += a; s2[c >> 2] += b;
        if (c < 25) {
            const int cn = c + 7;
            issue_chunk1k(rowbase + (size_t)(cn >> 2) * D + (cn & 3) * 256,
                          ring + (cn & 7) * 256, l);
        }
    }

    // batched fp32 butterfly
#pragma unroll
    for (int off = 16; off; off >>= 1) {
#pragma unroll
        for (int k = 0; k < 8; k++) {
            s1[k] += __shfl_xor_sync(0xffffffffu, s1[k], off);
            s2[k] += __shfl_xor_sync(0xffffffffu, s2[k], off);
        }
    }
#pragma unroll
    for (int k = 0; k < 8; k++) {
        if (l == k) {
            float var = (s2[k] - s1[k] * s1[k] * (1.0f / (float)D)) * (1.0f / (float)(D - 1));
            g_entropy[(size_t)n * S + row0 + k] = var > 0.f ? sqrtf(var) : 0.f;
        }
    }

    // deterministic column-sum combine (reuse sm[0..4096) as cs[4][1024])
    __syncthreads();
    float* cs = sm;
#pragma unroll
    for (int q = 0; q < 4; q++) {
        reinterpret_cast<float4*>(&cs[w * 1024 + q * 256 + 4 * l])[0]       = colacc[q * 2];
        reinterpret_cast<float4*>(&cs[w * 1024 + q * 256 + 4 * (l + 32)])[0] = colacc[q * 2 + 1];
    }
    __syncthreads();
#pragma unroll
    for (int g = 0; g < 8; g++) {
        const int d = t + 128 * g;
        g_part[(size_t)tileg * D + d] = ((cs[0 * 1024 + d] + cs[1 * 1024 + d]) +
                                         (cs[2 * 1024 + d] + cs[3 * 1024 + d]));
    }
    __syncthreads();                        // ring reuse on next tile
}

// ---------------- query init unit (32 rows): agg=query, out=0, col partials ---------
__device__ __noinline__ void query_init(const float* __restrict__ q,
                                        float* __restrict__ out, int qb)
{
    const int t = threadIdx.x;
    const int row0 = qb * 32;
    float cs[8];
#pragma unroll
    for (int g = 0; g < 8; g++) cs[g] = 0.f;
#pragma unroll 2
    for (int r = 0; r < 32; r++) {
        const size_t base = (size_t)(row0 + r) * D;
#pragma unroll
        for (int g = 0; g < 8; g++) {
            const int d = t + 128 * g;
            float v = q[base + d];
            cs[g] += v;
            g_agg[base + d] = v;
            out[base + d] = 0.f;
        }
    }
    const size_t pb = (size_t)(NMEM * RTILES + qb) * D;
#pragma unroll
    for (int g = 0; g < 8; g++) g_part[pb + t + 128 * g] = cs[g];
}

// ---------------- tail phase workers ------------------------------------------------
__device__ __noinline__ void scatter_mem(const float* __restrict__ mem, int n,
                                         const int* rows_s)
{
    const int t = threadIdx.x;
    const float* mb = mem + (size_t)n * S * D;
#pragma unroll
    for (int jb = 0; jb < 32; jb += 4) {
        float4 x[4], y[4];
#pragma unroll
        for (int j = 0; j < 4; j++) {
            const float4* rp = reinterpret_cast<const float4*>(mb + (size_t)rows_s[jb + j] * D);
            x[j] = rp[t]; y[j] = rp[t + 128];
        }
#pragma unroll
        for (int j = 0; j < 4; j++) {
            float* dst = g_agg + (size_t)rows_s[jb + j] * D;
            atomicAdd(dst + 4 * t + 0, trunc_clip(x[j].x));
            atomicAdd(dst + 4 * t + 1, trunc_clip(x[j].y));
            atomicAdd(dst + 4 * t + 2, trunc_clip(x[j].z));
            atomicAdd(dst + 4 * t + 3, trunc_clip(x[j].w));
            atomicAdd(dst + 512 + 4 * t + 0, trunc_clip(y[j].x));
            atomicAdd(dst + 512 + 4 * t + 1, trunc_clip(y[j].y));
            atomicAdd(dst + 512 + 4 * t + 2, trunc_clip(y[j].z));
            atomicAdd(dst + 512 + 4 * t + 3, trunc_clip(y[j].w));
        }
    }
}

__device__ __noinline__ void colmean_unit(int u)    // u = (source, quarter)
{
    const int t = threadIdx.x;
    const int n = u >> 2, qtr = u & 3;
#pragma unroll
    for (int g = 0; g < 2; g++) {
        const int d = qtr * 256 + g * 128 + t;
        const size_t base = (size_t)(n * RTILES) * D + d;
        float s = 0.f;
#pragma unroll 16
        for (int p = 0; p < RTILES; p++) s += g_part[base + (size_t)p * D];
        g_colmean[(size_t)n * D + d] = s * (1.0f / (float)S);
    }
}

__device__ __noinline__ void entropy_agg_fn(int bx)
{
    const int t = threadIdx.x, w = t >> 5, l = t & 31;
    for (int row = bx * 4 + w; row < S; row += 116 * 4) {
        const float4* rp = reinterpret_cast<const float4*>(g_agg + (size_t)row * D);
        float a = 0.f, bb = 0.f;
#pragma unroll
        for (int j = 0; j < 8; j++) {
            float4 x = rp[l + 32 * j];
            a += (x.x + x.y) + (x.z + x.w);
            bb += (x.x * x.x + x.y * x.y) + (x.z * x.z + x.w * x.w);
        }
#pragma unroll
        for (int off = 16; off; off >>= 1) {
            a += __shfl_xor_sync(0xffffffffu, a, off);
            bb += __shfl_xor_sync(0xffffffffu, bb, off);
        }
        if (l == 0) {
            float var = (bb - a * a * (1.0f / (float)D)) * (1.0f / (float)(D - 1));
            g_entropy2[row] = var > 0.f ? sqrtf(var) : 0.f;
        }
    }
}

__device__ __noinline__ void mlp1_fn(const float* __restrict__ W1, int c, float* sf)
{
    const int t = threadIdx.x;
    for (int idx = t; idx < (NMEM + 1) * 32; idx += 128) {
        const int n = idx >> 5, kk = idx & 31;
        sf[idx] = g_colmean[(size_t)n * D + c * 32 + kk];
    }
    __syncthreads();
    float acc[NMEM + 1];
#pragma unroll
    for (int n = 0; n <= NMEM; n++) acc[n] = 0.f;
#pragma unroll 4
    for (int kk = 0; kk < 32; kk++) {
        const float wv = W1[(size_t)(c * 32 + kk) * 128 + t];
#pragma unroll
        for (int n = 0; n <= NMEM; n++) acc[n] = fmaf(sf[n * 32 + kk], wv, acc[n]);
    }
#pragma unroll
    for (int n = 0; n <= NMEM; n++)
        g_h1p[(size_t)(c * (NMEM + 1) + n) * 128 + t] = acc[n];
    __syncthreads();
}

__device__ __noinline__ void mlp2_fn(const float* __restrict__ surprise,
                                     const float* __restrict__ W1,
                                     const float* __restrict__ b1,
                                     const float* __restrict__ W2,
                                     const float* __restrict__ b2,
                                     int m, float* H)     // m: (n, c of 8)
{
    const int t = threadIdx.x, w = t >> 5, l = t & 31;
    const int n = m >> 3, c = m & 7;
    float h = b1[t];
#pragma unroll 8
    for (int cc = 0; cc < 32; cc++)
        h += g_h1p[(size_t)(cc * (NMEM + 1) + n) * 128 + t];
    if (n < NMEM) h = fmaf(surprise[n], W1[(size_t)1024 * 128 + t], h);
    H[t] = h > 0.f ? h : 0.f;
    __syncthreads();
    const int d = c * 128 + t;
    float e0 = b2[d], e1 = 0.f, e2 = 0.f, e3 = 0.f;
    float e4 = 0.f, e5 = 0.f, e6 = 0.f, e7 = 0.f;
#pragma unroll 4
    for (int k = 0; k < 128; k += 8) {
        e0 = fmaf(H[k + 0], W2[(size_t)(k + 0) * D + d], e0);
        e1 = fmaf(H[k + 1], W2[(size_t)(k + 1) * D + d], e1);
        e2 = fmaf(H[k + 2], W2[(size_t)(k + 2) * D + d], e2);
        e3 = fmaf(H[k + 3], W2[(size_t)(k + 3) * D + d], e3);
        e4 = fmaf(H[k + 4], W2[(size_t)(k + 4) * D + d], e4);
        e5 = fmaf(H[k + 5], W2[(size_t)(k + 5) * D + d], e5);
        e6 = fmaf(H[k + 6], W2[(size_t)(k + 6) * D + d], e6);
        e7 = fmaf(H[k + 7], W2[(size_t)(k + 7) * D + d], e7);
    }
    const float e = ((e0 + e1) + (e2 + e3)) + ((e4 + e5) + (e6 + e7));
    g_emb[(size_t)n * D + d] = e;
    float nrm = e * e;
#pragma unroll
    for (int off = 16; off; off >>= 1) nrm += __shfl_xor_sync(0xffffffffu, nrm, off);
    __syncthreads();
    if (l == 0) H[w] = nrm;
    __syncthreads();
    if (t == 0) g_norm8[n * 8 + c] = (H[0] + H[1]) + (H[2] + H[3]);
    __syncthreads();
}

__device__ __noinline__ void sims_fn(const float* __restrict__ pm,
                                     float* __restrict__ out, float* ssim)
{
    const int t = threadIdx.x, w = t >> 5, l = t & 31;
    float nq2 = 0.f;
#pragma unroll
    for (int c = 0; c < 8; c++) nq2 += g_norm8[NMEM * 8 + c];
    const float nq = sqrtf(nq2);
#pragma unroll
    for (int mi = 0; mi < 8; mi++) {
        const int n = w * 8 + mi;
        const float4* en = reinterpret_cast<const float4*>(g_emb + (size_t)n * D) + l * 8;
        const float4* eq = reinterpret_cast<const float4*>(g_emb + (size_t)NMEM * D) + l * 8;
        float a0 = 0.f, a1 = 0.f, a2 = 0.f, a3 = 0.f;
#pragma unroll
        for (int j = 0; j < 8; j++) {
            float4 x = en[j], y = eq[j];
            a0 = fmaf(x.x, y.x, a0);
            a1 = fmaf(x.y, y.y, a1);
            a2 = fmaf(x.z, y.z, a2);
            a3 = fmaf(x.w, y.w, a3);
        }
        float p = (a0 + a1) + (a2 + a3);
#pragma unroll
        for (int off = 16; off; off >>= 1) p += __shfl_xor_sync(0xffffffffu, p, off);
        if (l == 0) {
            float nn2 = 0.f;
#pragma unroll
            for (int c = 0; c < 8; c++) nn2 += g_norm8[n * 8 + c];
            const float sim = p / (fmaxf(sqrtf(nn2), 1e-8f) * fmaxf(nq, 1e-8f)) * pm[n];
            out[(size_t)S * D + n] = sim;
            ssim[n] = sim;
        }
    }
    __syncthreads();
    if (t < NMEM) {
        const float v = ssim[t];
        int r = 0;
#pragma unroll
        for (int i = 0; i < NMEM; i++) {
            const float vi = ssim[i];
            r += ((vi > v) || (vi == v && i < t)) ? 1 : 0;
        }
        out[(size_t)S * D + NMEM + r] = (float)t;
    }
}

__device__ __noinline__ void recon_fn(float* __restrict__ out, int j)
{
    const int t = threadIdx.x;
    const int row = g_fidx[j];
    const float inv = 1.0f / 33.0f;
    const float4* src = reinterpret_cast<const float4*>(g_agg + (size_t)row * D);
    float4* dst = reinterpret_cast<float4*>(out + (size_t)row * D);
#pragma unroll
    for (int g = 0; g < 2; g++) {
        float4 x = src[t + 128 * g];
        float4 r;
        r.x = trunc_clip(x.x * inv);
        r.y = trunc_clip(x.y * inv);
        r.z = trunc_clip(x.z * inv);
        r.w = trunc_clip(x.w * inv);
        dst[t + 128 * g] = r;
    }
}

// =====================================================================================
// THE kernel: 148 blocks x 128 threads (1/SM), one launch, 4 grid barriers.
// =====================================================================================
__global__ void __launch_bounds__(128)
fused_kernel(const float* __restrict__ mem, const float* __restrict__ q,
             const float* __restrict__ surprise, const float* __restrict__ pm,
             const float* __restrict__ W1, const float* __restrict__ b1,
             const float* __restrict__ W2, const float* __restrict__ b2,
             float* __restrict__ out)
{
    __shared__ __align__(16) float sm[8192];    // 32KB static
    const int bx = blockIdx.x;

    // ---- stream phase: static assignment (deterministic g_part) --------------------
    for (int u = bx; u < 64 + NMEM * RTILES; u += NBLK) {
        if (u < 64) query_init(q, out, u);
        else        stream_tile(mem, u - 64, sm);
    }

    grid_barrier();

    // ---- Phase A: per-mem topk+scatter (0..31) | colmean (32..147) ------------------
    TopkScratch* sc = reinterpret_cast<TopkScratch*>(sm);
    int* rows_s = reinterpret_cast<int*>(sm + 4096);     // byte 16KB
    if (bx < 32) {
        topk_hist128(g_entropy + (size_t)bx * S, rows_s, sc);
        scatter_mem(mem, bx, rows_s);
    } else {
        for (int u = bx - 32; u < (NMEM + 1) * 4; u += NBLK - 32) colmean_unit(u);
    }

    grid_barrier();

    // ---- Phase B: entropy_agg (0..115) | mlp1 (116..147) ----------------------------
    if (bx < 116) entropy_agg_fn(bx);
    else          mlp1_fn(W1, bx - 116, sm);

    grid_barrier();

    // ---- Phase C: mlp2 (0..131, 2 units each) | final topk (132) --------------------
    if (bx < 132) {
        mlp2_fn(surprise, W1, b1, W2, b2, 2 * bx,     sm);
        mlp2_fn(surprise, W1, b1, W2, b2, 2 * bx + 1, sm);
    } else if (bx == 132) {
        topk_hist128(g_entropy2, rows_s, sc);
        if (threadIdx.x < PATCH) g_fidx[threadIdx.x] = rows_s[threadIdx.x];
    }

    grid_barrier();

    // ---- Phase D: recon (0..31) | sims+argsort (32) ---------------------------------
    if (bx < 32)       recon_fn(out, bx);
    else if (bx == 32) sims_fn(pm, out, sm);
}

// ---------------- launch ------------------------------------------------------------
extern "C" void kernel_launch(void* const* d_in, const int* in_sizes, int n_in,
                              void* d_out, int out_size)
{
    const float* query    = (const float*)d_in[0];
    const float* memories = (const float*)d_in[1];
    const float* surprise = (const float*)d_in[2];
    const float* pm       = (const float*)d_in[3];
    const float* W1       = (const float*)d_in[4];
    const float* b1       = (const float*)d_in[5];
    const float* W2       = (const float*)d_in[6];
    const float* b2       = (const float*)d_in[7];
    float* out = (float*)d_out;

    fused_kernel<<<NBLK, 128>>>(memories, query, surprise, pm,
                                W1, b1, W2, b2, out);
}

// round 16
// speedup vs baseline: 2.8336x; 2.8336x over previous
#include <cuda_runtime.h>
#include <cuda_bf16.h>
#include <float.h>
#include <math.h>

#define S 2048
#define D 1024
#define NMEM 32
#define PATCH 32
#define RTILES 64                 // tiles per memory (32 rows each)
#define K1B 164                   // tail grid (proven-safe barrier size)
#define CANDMAX 320

// ---------------- scratch (static device globals; no allocation) ----------------
__device__ float g_entropy [NMEM * S];
__device__ float g_entropy2[S];
__device__ float g_part    [(NMEM + 1) * RTILES * D];   // slot n*64+p (query n=32)
__device__ float g_colmean [(NMEM + 1) * D];
__device__ float g_agg     [S * D];                     // query + patches (= 33*aggregated)
__device__ float g_h1p     [32 * (NMEM + 1) * 128];
__device__ float g_emb     [(NMEM + 1) * D];
__device__ float g_norm4   [(NMEM + 1) * 4];
__device__ int   g_topidx  [NMEM * PATCH];
__device__ int   g_fidx    [PATCH];
__device__ float g_wsink;
__device__ unsigned g_cnt = 0;
__device__ volatile unsigned g_gen;

struct TopkScratch {
    int bins[1024];
    unsigned long long cb[CANDMAX];
    float rmin[8], rmax[8];
    float vmin, vmax;
    int cnt, thr, total;
};

// ---------------- cp.async helpers --------------------------------------------------
__device__ __forceinline__ void cp_async16(float* sdst, const float* gsrc)
{
    unsigned sa = (unsigned)__cvta_generic_to_shared(sdst);
    asm volatile("cp.async.cg.shared.global [%0], [%1], 16;" :: "r"(sa), "l"(gsrc) : "memory");
}
__device__ __forceinline__ void issue_chunk(const float* g, float* slot, int l)
{
#pragma unroll
    for (int j = 0; j < 4; j++)
        cp_async16(slot + (l + 32 * j) * 4, g + (l + 32 * j) * 4);
    asm volatile("cp.async.commit_group;" ::: "memory");
}

// =====================================================================================
// K0: fused big pass — VERBATIM the R11 winner (measured ~47us, at LTS cap).
// Blocks 0..2047: memory row entropy + column partials.
// Blocks 2048..2111: query -> g_agg copy, out zero, query column partials.
// =====================================================================================
__global__ void __launch_bounds__(128)
bigpass_kernel(const float* __restrict__ mem, const float* __restrict__ q,
               float* __restrict__ out)
{
    __shared__ float sm[8192];
    const int bx = blockIdx.x;
    const int t = threadIdx.x;
    const int w = t >> 5, l = t & 31;

    if (bx < NMEM * RTILES) {
        const int tile = bx & (RTILES - 1);
        const int n    = bx >> 6;
        const int row0 = tile * 32 + w * 8;
        const float* rowbase = mem + (size_t)n * S * D + (size_t)row0 * D;
        float* ring = sm + w * 2048;

        issue_chunk(rowbase + 0,         ring + 0 * 512, l);
        issue_chunk(rowbase + 512,       ring + 1 * 512, l);
        issue_chunk(rowbase + (size_t)D, ring + 2 * 512, l);

        float4 colacc[8];
#pragma unroll
        for (int j = 0; j < 8; j++) colacc[j] = make_float4(0.f, 0.f, 0.f, 0.f);
        float s1[8], s2[8];
#pragma unroll
        for (int k = 0; k < 8; k++) { s1[k] = 0.f; s2[k] = 0.f; }

#pragma unroll
        for (int k = 0; k < 16; k++) {
            if (k <= 13)      asm volatile("cp.async.wait_group 2;" ::: "memory");
            else if (k == 14) asm volatile("cp.async.wait_group 1;" ::: "memory");
            else              asm volatile("cp.async.wait_group 0;" ::: "memory");
            const float4* rp = reinterpret_cast<const float4*>(ring + (k & 3) * 512);
            const int half = k & 1;
            float a = 0.f, b = 0.f;
#pragma unroll
            for (int j = 0; j < 4; j++) {
                float4 x = rp[l + 32 * j];
                const int c = half * 4 + j;
                colacc[c].x += x.x; colacc[c].y += x.y; colacc[c].z += x.z; colacc[c].w += x.w;
                a += (x.x + x.y) + (x.z + x.w);
                b += (x.x * x.x + x.y * x.y) + (x.z * x.z + x.w * x.w);
            }
            s1[k >> 1] += a; s2[k >> 1] += b;
            if (k < 13) {
                const int kn = k + 3;
                issue_chunk(rowbase + (size_t)(kn >> 1) * D + (kn & 1) * 512,
                            ring + (kn & 3) * 512, l);
            }
        }

#pragma unroll
        for (int off = 16; off; off >>= 1) {
#pragma unroll
            for (int k = 0; k < 8; k++) {
                s1[k] += __shfl_xor_sync(0xffffffffu, s1[k], off);
                s2[k] += __shfl_xor_sync(0xffffffffu, s2[k], off);
            }
        }
#pragma unroll
        for (int k = 0; k < 8; k++) {
            if (l == k) {
                float var = (s2[k] - s1[k] * s1[k] * (1.0f / (float)D)) * (1.0f / (float)(D - 1));
                g_entropy[(size_t)n * S + row0 + k] = var > 0.f ? sqrtf(var) : 0.f;
            }
        }

        __syncthreads();
        float* cs = sm;
#pragma unroll
        for (int h = 0; h < 2; h++)
#pragma unroll
            for (int j = 0; j < 4; j++)
                reinterpret_cast<float4*>(&cs[w * 1024 + h * 512 + 4 * (l + 32 * j)])[0]
                    = colacc[h * 4 + j];
        __syncthreads();
#pragma unroll
        for (int g = 0; g < 8; g++) {
            const int d = t + 128 * g;
            g_part[(size_t)bx * D + d] = ((cs[0 * 1024 + d] + cs[1 * 1024 + d]) +
                                          (cs[2 * 1024 + d] + cs[3 * 1024 + d]));
        }
    } else {
        const int qb = bx - NMEM * RTILES;        // 0..63
        const int row0 = qb * 32;
        float cs[8];
#pragma unroll
        for (int g = 0; g < 8; g++) cs[g] = 0.f;
#pragma unroll 2
        for (int r = 0; r < 32; r++) {
            const size_t base = (size_t)(row0 + r) * D;
#pragma unroll
            for (int g = 0; g < 8; g++) {
                const int d = t + 128 * g;
                float v = q[base + d];
                cs[g] += v;
                g_agg[base + d] = v;
                out[base + d] = 0.f;
            }
        }
        const size_t pb = (size_t)(NMEM * RTILES + qb) * D;
#pragma unroll
        for (int g = 0; g < 8; g++) g_part[pb + t + 128 * g] = cs[g];
    }
}

// =====================================================================================
// K1: tail, 164 blocks x 256 threads, 4 grid barriers (5 phases).
// =====================================================================================
__device__ __forceinline__ void grid_barrier()
{
    __threadfence();
    __syncthreads();
    if (threadIdx.x == 0) {
        const unsigned gen0 = g_gen;
        __threadfence();
        if (atomicAdd(&g_cnt, 1) == gridDim.x - 1) {
            atomicExch(&g_cnt, 0);
            __threadfence();
            atomicAdd((unsigned*)&g_gen, 1);
        } else {
            while (g_gen == gen0) { __nanosleep(64); }
        }
    }
    __syncthreads();
    __threadfence();
}

__device__ __forceinline__ void hist_threshold(TopkScratch* sc, int t)
{
    const int w = t >> 5, l = t & 31;
    if (w == 0) {
        int gs = 0;
#pragma unroll
        for (int k = 0; k < 32; k++) gs += sc->bins[l * 32 + k];
        int suf = gs;
#pragma unroll
        for (int off = 1; off < 32; off <<= 1) {
            int o = __shfl_down_sync(0xffffffffu, suf, off);
            if (l + off < 32) suf += o;
        }
        int sufn = __shfl_down_sync(0xffffffffu, suf, 1);
        if (l == 31) sufn = 0;
        if (suf >= PATCH && sufn < PATCH) {
            int c = sufn, bb = 0;
            for (int k = 31; k >= 0; k--) {
                c += sc->bins[l * 32 + k];
                if (c >= PATCH) { bb = l * 32 + k; break; }
            }
            sc->thr = bb; sc->total = c;
        }
    }
}

// 256-thread exact top-32 of 2048 non-negative floats (histogram + exact rank)
__device__ void topk_hist256(const float* __restrict__ e, int* rows_s, TopkScratch* sc)
{
    const int t = threadIdx.x, w = t >> 5, l = t & 31;
    float v[8];
    float mn = FLT_MAX, mx = -FLT_MAX;
#pragma unroll
    for (int j = 0; j < 8; j++) {
        v[j] = e[t + 256 * j];
        mn = fminf(mn, v[j]);
        mx = fmaxf(mx, v[j]);
    }
#pragma unroll
    for (int off = 16; off; off >>= 1) {
        mn = fminf(mn, __shfl_xor_sync(0xffffffffu, mn, off));
        mx = fmaxf(mx, __shfl_xor_sync(0xffffffffu, mx, off));
    }
    if (l == 0) { sc->rmin[w] = mn; sc->rmax[w] = mx; }
#pragma unroll
    for (int j = 0; j < 4; j++) sc->bins[t + 256 * j] = 0;
    if (t == 0) sc->cnt = 0;
    __syncthreads();
    if (t == 0) {
        float a = sc->rmin[0], b = sc->rmax[0];
#pragma unroll
        for (int j = 1; j < 8; j++) { a = fminf(a, sc->rmin[j]); b = fmaxf(b, sc->rmax[j]); }
        sc->vmin = a; sc->vmax = b;
    }
    __syncthreads();
    const float vmin = sc->vmin;
    const float scale = 1023.0f / fmaxf(sc->vmax - vmin, 1e-30f);
    int bn[8];
#pragma unroll
    for (int j = 0; j < 8; j++) {
        int b = (int)((v[j] - vmin) * scale);
        bn[j] = b < 0 ? 0 : (b > 1023 ? 1023 : b);
        atomicAdd(&sc->bins[bn[j]], 1);
    }
    __syncthreads();
    hist_threshold(sc, t);
    __syncthreads();
    const int thr = sc->thr, total = sc->total;
    if (total <= CANDMAX) {
#pragma unroll
        for (int j = 0; j < 8; j++) {
            if (bn[j] >= thr) {
                int p = atomicAdd(&sc->cnt, 1);
                sc->cb[p] = ((unsigned long long)__float_as_uint(v[j]) << 32)
                            | (unsigned)(~(t + 256 * j));
            }
        }
        __syncthreads();
        for (int i = t; i < total; i += 256) {
            const unsigned long long k = sc->cb[i];
            int r = 0;
            for (int q = 0; q < total; q++) r += (sc->cb[q] > k) ? 1 : 0;
            if (r < PATCH) rows_s[r] = (int)(~(unsigned)k);
        }
        __syncthreads();
    } else {
        // exact rank-count fallback (degenerate data only)
#pragma unroll 1
        for (int j = 0; j < 8; j++) {
            const int idx = t + 256 * j;
            const unsigned long long k =
                ((unsigned long long)__float_as_uint(v[j]) << 32) | (unsigned)(~idx);
            int r = 0;
            for (int i = 0; i < S; i++) {
                const unsigned long long kk =
                    ((unsigned long long)__float_as_uint(e[i]) << 32) | (unsigned)(~i);
                r += (kk > k) ? 1 : 0;
            }
            if (r < PATCH) rows_s[r] = idx;
        }
        __syncthreads();
    }
}

__device__ __forceinline__ float trunc_clip(float x)
{
    return truncf(fminf(fmaxf(x, -128.f), 127.f));
}

__global__ void __launch_bounds__(256)
tail_kernel(const float* __restrict__ mem, const float* __restrict__ surprise,
            const float* __restrict__ pm,
            const float* __restrict__ W1, const float* __restrict__ b1,
            const float* __restrict__ W2, const float* __restrict__ b2,
            float* __restrict__ out)
{
    __shared__ TopkScratch sc;
    __shared__ int rows_s[PATCH];
    __shared__ float sf[(NMEM + 1) * 32];
    __shared__ float H[128];
    __shared__ float ssim[NMEM];

    const int b = blockIdx.x, t = threadIdx.x;
    const int w = t >> 5, l = t & 31;

    // ===== Phase A: per-mem topk (0..31) | colmean (32..97) | warm W1/W2 (98..163) ===
    if (b < 32) {
        topk_hist256(g_entropy + (size_t)b * S, rows_s, &sc);
        if (t < PATCH) g_topidx[b * PATCH + t] = rows_s[t];
    } else if (b < 98) {
        const int m = b - 32;                // source n, half hf
        const int n = m >> 1, hf = m & 1;
#pragma unroll
        for (int g = 0; g < 2; g++) {
            const int d = hf * 512 + g * 256 + t;
            const size_t base = (size_t)(n * RTILES) * D + d;
            float s = 0.f;
#pragma unroll 16
            for (int p = 0; p < RTILES; p++) s += g_part[base + (size_t)p * D];
            g_colmean[(size_t)n * D + d] = s * (1.0f / (float)S);
        }
    } else {
        const int j = b - 98;                // warm W1+W2 into L2
        float acc = 0.f;
        for (int i = j * 256 + t; i < 1027 * 128; i += 66 * 256) acc += W1[i];
        for (int i = j * 256 + t; i < 128 * D;    i += 66 * 256) acc += W2[i];
        if (acc == 1.2345678e30f) g_wsink = acc;   // never true; defeats DCE
    }

    grid_barrier();

    // ===== Phase B: scatter spread across ALL blocks (1024 rows total) ===============
    for (int f = b; f < NMEM * PATCH; f += K1B) {
        const int n = f >> 5;
        const int row = g_topidx[f];
        float4 x = reinterpret_cast<const float4*>(mem + ((size_t)n * S + row) * D)[t];
        float* dst = g_agg + (size_t)row * D + 4 * t;
        atomicAdd(dst + 0, trunc_clip(x.x));
        atomicAdd(dst + 1, trunc_clip(x.y));
        atomicAdd(dst + 2, trunc_clip(x.z));
        atomicAdd(dst + 3, trunc_clip(x.w));
    }

    grid_barrier();

    // ===== Phase C: entropy_agg (0..127) | mlp1 (128..159) ===========================
    if (b < 128) {
#pragma unroll
        for (int r = 0; r < 2; r++) {
            const int row = b * 16 + w * 2 + r;
            const float4* rp = reinterpret_cast<const float4*>(g_agg + (size_t)row * D);
            float a = 0.f, bb = 0.f;
#pragma unroll
            for (int j = 0; j < 8; j++) {
                float4 x = rp[l + 32 * j];
                a += (x.x + x.y) + (x.z + x.w);
                bb += (x.x * x.x + x.y * x.y) + (x.z * x.z + x.w * x.w);
            }
#pragma unroll
            for (int off = 16; off; off >>= 1) {
                a += __shfl_xor_sync(0xffffffffu, a, off);
                bb += __shfl_xor_sync(0xffffffffu, bb, off);
            }
            if (l == 0) {
                float var = (bb - a * a * (1.0f / (float)D)) * (1.0f / (float)(D - 1));
                g_entropy2[row] = var > 0.f ? sqrtf(var) : 0.f;
            }
        }
    } else if (b < 160) {
        const int c = b - 128;               // mlp1 K-chunk: W1 rows [c*32, c*32+32)
        for (int idx = t; idx < (NMEM + 1) * 32; idx += 256) {
            const int n = idx >> 5, kk = idx & 31;
            sf[idx] = g_colmean[(size_t)n * D + c * 32 + kk];
        }
        __syncthreads();
        if (t < 128) {
            float acc[NMEM + 1];
#pragma unroll
            for (int n = 0; n <= NMEM; n++) acc[n] = 0.f;
#pragma unroll 4
            for (int kk = 0; kk < 32; kk++) {
                const float wv = W1[(size_t)(c * 32 + kk) * 128 + t];
#pragma unroll
                for (int n = 0; n <= NMEM; n++) acc[n] = fmaf(sf[n * 32 + kk], wv, acc[n]);
            }
#pragma unroll
            for (int n = 0; n <= NMEM; n++)
                g_h1p[(size_t)(c * (NMEM + 1) + n) * 128 + t] = acc[n];
        }
    }

    grid_barrier();

    // ===== Phase D: mlp2 (0..131) | final topk (132) =================================
    if (b < 132) {
        const int n = b >> 2, c = b & 3;
        if (t < 128) {
            float h = b1[t];
#pragma unroll 8
            for (int cc = 0; cc < 32; cc++)
                h += g_h1p[(size_t)(cc * (NMEM + 1) + n) * 128 + t];
            if (n < NMEM) h = fmaf(surprise[n], W1[(size_t)1024 * 128 + t], h);
            H[t] = h > 0.f ? h : 0.f;
        }
        __syncthreads();
        const int d = c * 256 + t;
        float e0 = b2[d], e1 = 0.f, e2 = 0.f, e3 = 0.f;
        float e4 = 0.f, e5 = 0.f, e6 = 0.f, e7 = 0.f;
#pragma unroll 4
        for (int k = 0; k < 128; k += 8) {
            e0 = fmaf(H[k + 0], W2[(size_t)(k + 0) * D + d], e0);
            e1 = fmaf(H[k + 1], W2[(size_t)(k + 1) * D + d], e1);
            e2 = fmaf(H[k + 2], W2[(size_t)(k + 2) * D + d], e2);
            e3 = fmaf(H[k + 3], W2[(size_t)(k + 3) * D + d], e3);
            e4 = fmaf(H[k + 4], W2[(size_t)(k + 4) * D + d], e4);
            e5 = fmaf(H[k + 5], W2[(size_t)(k + 5) * D + d], e5);
            e6 = fmaf(H[k + 6], W2[(size_t)(k + 6) * D + d], e6);
            e7 = fmaf(H[k + 7], W2[(size_t)(k + 7) * D + d], e7);
        }
        const float e = ((e0 + e1) + (e2 + e3)) + ((e4 + e5) + (e6 + e7));
        g_emb[(size_t)n * D + d] = e;
        float nrm = e * e;
#pragma unroll
        for (int off = 16; off; off >>= 1) nrm += __shfl_xor_sync(0xffffffffu, nrm, off);
        __syncthreads();                     // reuse H as reduction scratch
        if (l == 0) H[w] = nrm;
        __syncthreads();
        if (t == 0)
            g_norm4[n * 4 + c] = ((H[0] + H[1]) + (H[2] + H[3])) +
                                 ((H[4] + H[5]) + (H[6] + H[7]));
    } else if (b == 132) {
        topk_hist256(g_entropy2, rows_s, &sc);
        if (t < PATCH) g_fidx[t] = rows_s[t];
    }

    grid_barrier();

    // ===== Phase E: recon (0..31) | sims+argsort (32) ================================
    if (b < 32) {
        const int row = g_fidx[b];
        const float inv = 1.0f / 33.0f;
        float4 x = reinterpret_cast<const float4*>(g_agg + (size_t)row * D)[t];
        float4 r;
        r.x = trunc_clip(x.x * inv);
        r.y = trunc_clip(x.y * inv);
        r.z = trunc_clip(x.z * inv);
        r.w = trunc_clip(x.w * inv);
        reinterpret_cast<float4*>(out + (size_t)row * D)[t] = r;
    } else if (b == 32) {
        const float nq = sqrtf((g_norm4[NMEM * 4 + 0] + g_norm4[NMEM * 4 + 1]) +
                               (g_norm4[NMEM * 4 + 2] + g_norm4[NMEM * 4 + 3]));
#pragma unroll
        for (int mi = 0; mi < 4; mi++) {
            const int n = w + 8 * mi;
            const float4* en = reinterpret_cast<const float4*>(g_emb + (size_t)n * D) + l * 8;
            const float4* eq = reinterpret_cast<const float4*>(g_emb + (size_t)NMEM * D) + l * 8;
            float a0 = 0.f, a1 = 0.f, a2 = 0.f, a3 = 0.f;
#pragma unroll
            for (int j = 0; j < 8; j++) {
                float4 x = en[j], y = eq[j];
                a0 = fmaf(x.x, y.x, a0);
                a1 = fmaf(x.y, y.y, a1);
                a2 = fmaf(x.z, y.z, a2);
                a3 = fmaf(x.w, y.w, a3);
            }
            float p = (a0 + a1) + (a2 + a3);
#pragma unroll
            for (int off = 16; off; off >>= 1) p += __shfl_xor_sync(0xffffffffu, p, off);
            if (l == 0) {
                const float nn = sqrtf((g_norm4[n * 4 + 0] + g_norm4[n * 4 + 1]) +
                                       (g_norm4[n * 4 + 2] + g_norm4[n * 4 + 3]));
                const float sim = p / (fmaxf(nn, 1e-8f) * fmaxf(nq, 1e-8f)) * pm[n];
                out[(size_t)S * D + n] = sim;
                ssim[n] = sim;
            }
        }
        __syncthreads();
        if (t < NMEM) {
            const float v = ssim[t];
            int r = 0;
#pragma unroll
            for (int i = 0; i < NMEM; i++) {
                const float vi = ssim[i];
                r += ((vi > v) || (vi == v && i < t)) ? 1 : 0;
            }
            out[(size_t)S * D + NMEM + r] = (float)t;
        }
    }
}

// ---------------- launch ------------------------------------------------------------
extern "C" void kernel_launch(void* const* d_in, const int* in_sizes, int n_in,
                              void* d_out, int out_size)
{
    const float* query    = (const float*)d_in[0];
    const float* memories = (const float*)d_in[1];
    const float* surprise = (const float*)d_in[2];
    const float* pm       = (const float*)d_in[3];
    const float* W1       = (const float*)d_in[4];
    const float* b1       = (const float*)d_in[5];
    const float* W2       = (const float*)d_in[6];
    const float* b2       = (const float*)d_in[7];
    float* out = (float*)d_out;

    // K0: 268MB memory pass + query init (proven 47us, at LTS cap)
    bigpass_kernel<<<NMEM * RTILES + 64, 128>>>(memories, query, out);
    // K1: 5-phase tail with parallel scatter
    tail_kernel<<<K1B, 256>>>(memories, surprise, pm, W1, b1, W2, b2, out);
}